// round 1
// baseline (speedup 1.0000x reference)
#include <cuda_runtime.h>
#include <math.h>

// Problem constants
// B=4, T=2048, C=2048, NH=16, NKV=4, HD=128

// Scratch (allocation-free rule: __device__ globals)
__device__ float g_q[(size_t)4 * 16 * 2048 * 128];   // [B,16,T,128]
__device__ float g_k[(size_t)4 * 4 * 2048 * 128];    // [B,4,T,128]
__device__ float g_v[(size_t)4 * 4 * 2048 * 128];    // [B,4,T,128]
__device__ float g_attn[(size_t)4 * 2048 * 2048];    // [B,T,C]

// ---------------------------------------------------------------------------
// Fused QKV projection: C[m,n] = sum_k X[m,k] * W[n,k]
// m in [0,8192) = (b,t); n in [0,3072): [0,2048)->Q, [2048,2560)->K, rest->V
// BM=BN=128, BK=16, 256 threads, 8x8 per thread.
// ---------------------------------------------------------------------------
__global__ __launch_bounds__(256) void qkv_gemm_kernel(
    const float* __restrict__ X,
    const float* __restrict__ Wq,
    const float* __restrict__ Wk,
    const float* __restrict__ Wv)
{
    __shared__ float As[16 * 132];
    __shared__ float Bs[16 * 132];

    const int tid = threadIdx.x;
    const int m0 = blockIdx.y * 128;
    const int n0 = blockIdx.x * 128;

    const float* Bmat;
    int nb;
    if (n0 < 2048)      { Bmat = Wq; nb = n0; }
    else if (n0 < 2560) { Bmat = Wk; nb = n0 - 2048; }
    else                { Bmat = Wv; nb = n0 - 2560; }

    const int tr = tid >> 4;   // 0..15
    const int tc = tid & 15;   // 0..15

    float acc[8][8];
#pragma unroll
    for (int i = 0; i < 8; i++)
#pragma unroll
        for (int j = 0; j < 8; j++) acc[i][j] = 0.f;

    for (int k0 = 0; k0 < 2048; k0 += 16) {
#pragma unroll
        for (int u = 0; u < 2; u++) {
            int f = tid + u * 256;
            int row = f >> 2;
            int kv = f & 3;
            float4 av = *(const float4*)(X + (size_t)(m0 + row) * 2048 + k0 + kv * 4);
            float4 bv = *(const float4*)(Bmat + (size_t)(nb + row) * 2048 + k0 + kv * 4);
            As[(kv * 4 + 0) * 132 + row] = av.x;
            As[(kv * 4 + 1) * 132 + row] = av.y;
            As[(kv * 4 + 2) * 132 + row] = av.z;
            As[(kv * 4 + 3) * 132 + row] = av.w;
            Bs[(kv * 4 + 0) * 132 + row] = bv.x;
            Bs[(kv * 4 + 1) * 132 + row] = bv.y;
            Bs[(kv * 4 + 2) * 132 + row] = bv.z;
            Bs[(kv * 4 + 3) * 132 + row] = bv.w;
        }
        __syncthreads();
#pragma unroll
        for (int kk = 0; kk < 16; kk++) {
            float a[8], b[8];
            *(float4*)&a[0] = *(const float4*)&As[kk * 132 + tr * 8];
            *(float4*)&a[4] = *(const float4*)&As[kk * 132 + tr * 8 + 4];
            *(float4*)&b[0] = *(const float4*)&Bs[kk * 132 + tc * 8];
            *(float4*)&b[4] = *(const float4*)&Bs[kk * 132 + tc * 8 + 4];
#pragma unroll
            for (int i = 0; i < 8; i++)
#pragma unroll
                for (int j = 0; j < 8; j++)
                    acc[i][j] = fmaf(a[i], b[j], acc[i][j]);
        }
        __syncthreads();
    }

    // Epilogue: scatter into [B,H,T,D] layouts. n0 is a multiple of 128 and
    // HEAD_DIM == 128, so each block column tile maps to exactly one head.
#pragma unroll
    for (int i = 0; i < 8; i++) {
        int m = m0 + tr * 8 + i;
        int bb = m >> 11;
        int t = m & 2047;
        float* dst;
        if (n0 < 2048) {
            int h = n0 >> 7;
            dst = g_q + (((size_t)(bb * 16 + h) * 2048 + t) * 128);
        } else if (n0 < 2560) {
            int h = (n0 - 2048) >> 7;
            dst = g_k + (((size_t)(bb * 4 + h) * 2048 + t) * 128);
        } else {
            int h = (n0 - 2560) >> 7;
            dst = g_v + (((size_t)(bb * 4 + h) * 2048 + t) * 128);
        }
        float4 o0 = make_float4(acc[i][0], acc[i][1], acc[i][2], acc[i][3]);
        float4 o1 = make_float4(acc[i][4], acc[i][5], acc[i][6], acc[i][7]);
        *(float4*)(dst + tc * 8)     = o0;
        *(float4*)(dst + tc * 8 + 4) = o1;
    }
}

// ---------------------------------------------------------------------------
// RoPE (interleaved pairs). H=16 -> g_q (also folds 1/sqrt(128) score scale),
// H=4 -> g_k.
// ---------------------------------------------------------------------------
template <int H, bool SCALE>
__global__ __launch_bounds__(256) void rope_kernel(
    const float* __restrict__ cosT, const float* __restrict__ sinT)
{
    size_t idx = (size_t)blockIdx.x * blockDim.x + threadIdx.x;
    size_t total = (size_t)4 * H * 2048 * 64;
    if (idx >= total) return;
    int i = (int)(idx & 63);
    size_t row = idx >> 6;             // (b*H + h)*2048 + t
    int t = (int)(row & 2047);
    float* ptr = (H == 16 ? g_q : g_k) + row * 128 + i * 2;
    float e = ptr[0], o = ptr[1];
    float c = cosT[t * 64 + i];
    float s = sinT[t * 64 + i];
    float ne = e * c - o * s;
    float no = e * s + o * c;
    if (SCALE) {
        const float sc = 0.08838834764831845f;   // 1/sqrt(128)
        ne *= sc; no *= sc;
    }
    ptr[0] = ne;
    ptr[1] = no;
}

// ---------------------------------------------------------------------------
// Causal flash attention, fp32. 64 q-rows x 64 k-cols per tile, D=128.
// grid (32, 16, 4), 256 threads. Q pre-scaled by 1/sqrt(128).
// Dynamic smem: Qs/Ks/Vs [64][132], Ss [64][68], stats 3x64.
// ---------------------------------------------------------------------------
#define FD 132
#define SD 68

__global__ __launch_bounds__(256) void flash_attn_kernel()
{
    extern __shared__ float sm[];
    float* Qs  = sm;                 // 64*FD
    float* Ks  = Qs + 64 * FD;       // 64*FD
    float* Vs  = Ks + 64 * FD;       // 64*FD
    float* Ss  = Vs + 64 * FD;       // 64*SD
    float* ms  = Ss + 64 * SD;       // 64
    float* ls  = ms + 64;            // 64
    float* als = ls + 64;            // 64

    const int tid = threadIdx.x;
    const int b = blockIdx.z;
    const int h = blockIdx.y;
    const int qt = blockIdx.x;
    const int q0 = qt * 64;
    const int kvh = h >> 2;

    const float* qptr = g_q + (((size_t)(b * 16 + h) * 2048 + q0) * 128);
    const float* kbase = g_k + ((size_t)(b * 4 + kvh) * 2048) * 128;
    const float* vbase = g_v + ((size_t)(b * 4 + kvh) * 2048) * 128;

    // load Q tile
#pragma unroll
    for (int u = 0; u < 8; u++) {
        int f = tid + u * 256;
        int r = f >> 5, dv = f & 31;
        *(float4*)&Qs[r * FD + dv * 4] = *(const float4*)(qptr + (size_t)r * 128 + dv * 4);
    }
    if (tid < 64) { ms[tid] = -1e30f; ls[tid] = 0.f; }

    const int ro = tid >> 4;   // 0..15, owns S/O rows ro*4..+3
    const int co = tid & 15;   // S cols co*4..+3, O cols co*8..+7
    float oacc[4][8];
#pragma unroll
    for (int i = 0; i < 4; i++)
#pragma unroll
        for (int c = 0; c < 8; c++) oacc[i][c] = 0.f;

    __syncthreads();

    for (int kt = 0; kt <= qt; kt++) {
        const float* kp = kbase + (size_t)kt * 64 * 128;
        const float* vp = vbase + (size_t)kt * 64 * 128;
#pragma unroll
        for (int u = 0; u < 8; u++) {
            int f = tid + u * 256;
            int r = f >> 5, dv = f & 31;
            *(float4*)&Ks[r * FD + dv * 4] = *(const float4*)(kp + (size_t)r * 128 + dv * 4);
            *(float4*)&Vs[r * FD + dv * 4] = *(const float4*)(vp + (size_t)r * 128 + dv * 4);
        }
        __syncthreads();

        // S = Q K^T
        float s[4][4];
#pragma unroll
        for (int i = 0; i < 4; i++)
#pragma unroll
            for (int j = 0; j < 4; j++) s[i][j] = 0.f;

        for (int d4 = 0; d4 < 32; d4++) {
            float4 qv[4], kv[4];
#pragma unroll
            for (int i = 0; i < 4; i++)
                qv[i] = *(const float4*)&Qs[(ro * 4 + i) * FD + d4 * 4];
#pragma unroll
            for (int j = 0; j < 4; j++)
                kv[j] = *(const float4*)&Ks[(co * 4 + j) * FD + d4 * 4];
#pragma unroll
            for (int i = 0; i < 4; i++)
#pragma unroll
                for (int j = 0; j < 4; j++) {
                    s[i][j] = fmaf(qv[i].x, kv[j].x, s[i][j]);
                    s[i][j] = fmaf(qv[i].y, kv[j].y, s[i][j]);
                    s[i][j] = fmaf(qv[i].z, kv[j].z, s[i][j]);
                    s[i][j] = fmaf(qv[i].w, kv[j].w, s[i][j]);
                }
        }

        if (kt == qt) {
            // diagonal tile: mask k > q
#pragma unroll
            for (int i = 0; i < 4; i++)
#pragma unroll
                for (int j = 0; j < 4; j++)
                    if (co * 4 + j > ro * 4 + i) s[i][j] = -1e30f;
        }
#pragma unroll
        for (int i = 0; i < 4; i++)
#pragma unroll
            for (int j = 0; j < 4; j++)
                Ss[(ro * 4 + i) * SD + co * 4 + j] = s[i][j];
        __syncthreads();

        // online softmax row update (64 threads, one per row)
        if (tid < 64) {
            int r = tid;
            float mo = ms[r];
            float mn = mo;
#pragma unroll 8
            for (int j = 0; j < 64; j++) mn = fmaxf(mn, Ss[r * SD + j]);
            float al = __expf(mo - mn);
            float sum = 0.f;
#pragma unroll 8
            for (int j = 0; j < 64; j++) {
                float p = __expf(Ss[r * SD + j] - mn);
                Ss[r * SD + j] = p;
                sum += p;
            }
            ls[r] = ls[r] * al + sum;
            ms[r] = mn;
            als[r] = al;
        }
        __syncthreads();

        // O = O*alpha + P V
        float al[4];
#pragma unroll
        for (int i = 0; i < 4; i++) al[i] = als[ro * 4 + i];
#pragma unroll
        for (int i = 0; i < 4; i++)
#pragma unroll
            for (int c = 0; c < 8; c++) oacc[i][c] *= al[i];

        for (int j = 0; j < 64; j++) {
            float p[4];
#pragma unroll
            for (int i = 0; i < 4; i++) p[i] = Ss[(ro * 4 + i) * SD + j];
            float4 v0 = *(const float4*)&Vs[j * FD + co * 8];
            float4 v1 = *(const float4*)&Vs[j * FD + co * 8 + 4];
#pragma unroll
            for (int i = 0; i < 4; i++) {
                oacc[i][0] = fmaf(p[i], v0.x, oacc[i][0]);
                oacc[i][1] = fmaf(p[i], v0.y, oacc[i][1]);
                oacc[i][2] = fmaf(p[i], v0.z, oacc[i][2]);
                oacc[i][3] = fmaf(p[i], v0.w, oacc[i][3]);
                oacc[i][4] = fmaf(p[i], v1.x, oacc[i][4]);
                oacc[i][5] = fmaf(p[i], v1.y, oacc[i][5]);
                oacc[i][6] = fmaf(p[i], v1.z, oacc[i][6]);
                oacc[i][7] = fmaf(p[i], v1.w, oacc[i][7]);
            }
        }
        __syncthreads();
    }

    // write normalized O to g_attn in [B,T,C] layout
#pragma unroll
    for (int i = 0; i < 4; i++) {
        int r = ro * 4 + i;
        float inv = 1.f / ls[r];
        int t = q0 + r;
        float* dst = g_attn + ((size_t)(b * 2048 + t) * 2048) + h * 128 + co * 8;
        float4 o0 = make_float4(oacc[i][0] * inv, oacc[i][1] * inv,
                                oacc[i][2] * inv, oacc[i][3] * inv);
        float4 o1 = make_float4(oacc[i][4] * inv, oacc[i][5] * inv,
                                oacc[i][6] * inv, oacc[i][7] * inv);
        *(float4*)(dst)     = o0;
        *(float4*)(dst + 4) = o1;
    }
}

// ---------------------------------------------------------------------------
// Output projection: out[m,n] = sum_k g_attn[m,k] * Wo[n,k]
// ---------------------------------------------------------------------------
__global__ __launch_bounds__(256) void out_gemm_kernel(
    const float* __restrict__ Wo, float* __restrict__ out)
{
    __shared__ float As[16 * 132];
    __shared__ float Bs[16 * 132];

    const int tid = threadIdx.x;
    const int m0 = blockIdx.y * 128;
    const int n0 = blockIdx.x * 128;
    const int tr = tid >> 4;
    const int tc = tid & 15;

    float acc[8][8];
#pragma unroll
    for (int i = 0; i < 8; i++)
#pragma unroll
        for (int j = 0; j < 8; j++) acc[i][j] = 0.f;

    for (int k0 = 0; k0 < 2048; k0 += 16) {
#pragma unroll
        for (int u = 0; u < 2; u++) {
            int f = tid + u * 256;
            int row = f >> 2;
            int kv = f & 3;
            float4 av = *(const float4*)(g_attn + (size_t)(m0 + row) * 2048 + k0 + kv * 4);
            float4 bv = *(const float4*)(Wo + (size_t)(n0 + row) * 2048 + k0 + kv * 4);
            As[(kv * 4 + 0) * 132 + row] = av.x;
            As[(kv * 4 + 1) * 132 + row] = av.y;
            As[(kv * 4 + 2) * 132 + row] = av.z;
            As[(kv * 4 + 3) * 132 + row] = av.w;
            Bs[(kv * 4 + 0) * 132 + row] = bv.x;
            Bs[(kv * 4 + 1) * 132 + row] = bv.y;
            Bs[(kv * 4 + 2) * 132 + row] = bv.z;
            Bs[(kv * 4 + 3) * 132 + row] = bv.w;
        }
        __syncthreads();
#pragma unroll
        for (int kk = 0; kk < 16; kk++) {
            float a[8], b[8];
            *(float4*)&a[0] = *(const float4*)&As[kk * 132 + tr * 8];
            *(float4*)&a[4] = *(const float4*)&As[kk * 132 + tr * 8 + 4];
            *(float4*)&b[0] = *(const float4*)&Bs[kk * 132 + tc * 8];
            *(float4*)&b[4] = *(const float4*)&Bs[kk * 132 + tc * 8 + 4];
#pragma unroll
            for (int i = 0; i < 8; i++)
#pragma unroll
                for (int j = 0; j < 8; j++)
                    acc[i][j] = fmaf(a[i], b[j], acc[i][j]);
        }
        __syncthreads();
    }

#pragma unroll
    for (int i = 0; i < 8; i++) {
        int m = m0 + tr * 8 + i;
        float* dst = out + (size_t)m * 2048 + n0 + tc * 8;
        float4 o0 = make_float4(acc[i][0], acc[i][1], acc[i][2], acc[i][3]);
        float4 o1 = make_float4(acc[i][4], acc[i][5], acc[i][6], acc[i][7]);
        *(float4*)(dst)     = o0;
        *(float4*)(dst + 4) = o1;
    }
}

// ---------------------------------------------------------------------------
extern "C" void kernel_launch(void* const* d_in, const int* in_sizes, int n_in,
                              void* d_out, int out_size)
{
    const float* x    = (const float*)d_in[0];
    const float* wq   = (const float*)d_in[1];
    const float* wk   = (const float*)d_in[2];
    const float* wv   = (const float*)d_in[3];
    const float* wo   = (const float*)d_in[4];
    const float* rc   = (const float*)d_in[5];
    const float* rs   = (const float*)d_in[6];
    float* out = (float*)d_out;

    (void)in_sizes; (void)n_in; (void)out_size;

    // 1. Fused QKV projection into [B,H,T,D] scratch
    qkv_gemm_kernel<<<dim3(24, 64), 256>>>(x, wq, wk, wv);

    // 2. RoPE (Q also gets 1/sqrt(128) folded in)
    rope_kernel<16, true ><<<(4 * 16 * 2048 * 64 + 255) / 256, 256>>>(rc, rs);
    rope_kernel<4,  false><<<(4 * 4  * 2048 * 64 + 255) / 256, 256>>>(rc, rs);

    // 3. Causal flash attention -> g_attn [B,T,C]
    const int smem_bytes = (3 * 64 * FD + 64 * SD + 3 * 64) * (int)sizeof(float);
    cudaFuncSetAttribute(flash_attn_kernel,
                         cudaFuncAttributeMaxDynamicSharedMemorySize, smem_bytes);
    flash_attn_kernel<<<dim3(32, 16, 4), 256, smem_bytes>>>();

    // 4. Output projection -> d_out
    out_gemm_kernel<<<dim3(16, 64), 256>>>(wo, out);
}

// round 3
// speedup vs baseline: 1.3525x; 1.3525x over previous
#include <cuda_runtime.h>
#include <math.h>
#include <cstdint>

// Problem constants: B=4, T=2048, C=2048, NH=16, NKV=4, HD=128

// Scratch (allocation-free rule: __device__ globals)
__device__ float g_q[(size_t)4 * 16 * 2048 * 128];   // [B,16,T,128]
__device__ float g_k[(size_t)4 * 4 * 2048 * 128];    // [B,4,T,128]
__device__ float g_v[(size_t)4 * 4 * 2048 * 128];    // [B,4,T,128]
__device__ float g_attn[(size_t)4 * 2048 * 2048];    // [B,T,C]

// ===========================================================================
// mma.sync tf32 helpers (plain sm_80+ PTX -- valid for non-'a' sm_103 target)
// ===========================================================================
__device__ __forceinline__ uint32_t f2tf32(float v) {
    uint32_t r;
    asm("cvt.rna.tf32.f32 %0, %1;" : "=r"(r) : "f"(v));
    return r;
}

__device__ __forceinline__ void mma_tf32_16x8x8(float* c, const uint32_t* a,
                                                const uint32_t* b) {
    asm volatile(
        "mma.sync.aligned.m16n8k8.row.col.f32.tf32.tf32.f32 "
        "{%0,%1,%2,%3}, {%4,%5,%6,%7}, {%8,%9}, {%0,%1,%2,%3};"
        : "+f"(c[0]), "+f"(c[1]), "+f"(c[2]), "+f"(c[3])
        : "r"(a[0]), "r"(a[1]), "r"(a[2]), "r"(a[3]), "r"(b[0]), "r"(b[1]));
}

// ===========================================================================
// tf32 GEMM mainloop: computes a 128x128 tile of C = A * B^T, where
// A[128, 2048] (K-major rows) and B[128, 2048] (K-major rows, i.e. C=A·Bᵀ).
// 256 threads (8 warps). Each warp owns a 64x32 subtile:
//   wm = wid&1 (2 row groups of 64), wn = wid>>1 (4 col groups of 32).
// BK=32 per chunk, double buffered. SMEM tiles stored [row][k] with stride 36
// (conflict-free fragment loads), values pre-converted to tf32.
// SMEM: 4 buffers of 128*36 words = 4*18432B = 73728B.
// ===========================================================================
#define SAS 36
#define TILE_WORDS (128 * SAS)
#define GEMM_SMEM_BYTES (4 * TILE_WORDS * 4)
#define NCH 64

struct Frag { float acc[4][4][4]; };   // [mt][nt][4]

__device__ __forceinline__ void store_tile(uint32_t* dst, const float4* v) {
    const int tid = threadIdx.x;
#pragma unroll
    for (int u = 0; u < 4; u++) {
        int f = tid + u * 256;          // 0..1023
        int row = f >> 3;               // 0..127
        int c4 = f & 7;                 // 0..7
        uint4 w;
        w.x = f2tf32(v[u].x); w.y = f2tf32(v[u].y);
        w.z = f2tf32(v[u].z); w.w = f2tf32(v[u].w);
        *(uint4*)(dst + row * SAS + c4 * 4) = w;
    }
}

__device__ __forceinline__ void load_global(float4* v, const float* __restrict__ src) {
    const int tid = threadIdx.x;
#pragma unroll
    for (int u = 0; u < 4; u++) {
        int f = tid + u * 256;
        int row = f >> 3;
        int c4 = f & 7;
        v[u] = *(const float4*)(src + (size_t)row * 2048 + c4 * 4);
    }
}

__device__ __forceinline__ void gemm_mainloop(const float* __restrict__ Ag,
                                              const float* __restrict__ Bg,
                                              uint32_t* smem, Frag& fr)
{
    const int tid = threadIdx.x;
    const int wid = tid >> 5;
    const int lane = tid & 31;
    const int wm = wid & 1;        // 0..1
    const int wn = wid >> 1;       // 0..3
    const int gr = lane >> 2;      // 0..7
    const int gc = lane & 3;       // 0..3

    uint32_t* bufA[2] = { smem, smem + 2 * TILE_WORDS };
    uint32_t* bufB[2] = { smem + TILE_WORDS, smem + 3 * TILE_WORDS };

#pragma unroll
    for (int mt = 0; mt < 4; mt++)
#pragma unroll
        for (int nt = 0; nt < 4; nt++)
#pragma unroll
            for (int i = 0; i < 4; i++) fr.acc[mt][nt][i] = 0.f;

    // preload chunk 0
    {
        float4 va[4], vb[4];
        load_global(va, Ag);
        load_global(vb, Bg);
        store_tile(bufA[0], va);
        store_tile(bufB[0], vb);
    }
    __syncthreads();

    for (int c = 0; c < NCH; c++) {
        const int cur = c & 1;

        // prefetch next chunk into registers (overlaps with MMA compute)
        float4 va[4], vb[4];
        if (c + 1 < NCH) {
            load_global(va, Ag + (c + 1) * 32);
            load_global(vb, Bg + (c + 1) * 32);
        }

        const uint32_t* As = bufA[cur];
        const uint32_t* Bs = bufB[cur];
#pragma unroll
        for (int ks = 0; ks < 4; ks++) {
            const int kb = ks * 8;
            uint32_t afr[4][4];
            uint32_t bfr[4][2];
#pragma unroll
            for (int mt = 0; mt < 4; mt++) {
                const int R = wm * 64 + mt * 16;
                afr[mt][0] = As[(R + gr) * SAS + kb + gc];
                afr[mt][1] = As[(R + gr + 8) * SAS + kb + gc];
                afr[mt][2] = As[(R + gr) * SAS + kb + gc + 4];
                afr[mt][3] = As[(R + gr + 8) * SAS + kb + gc + 4];
            }
#pragma unroll
            for (int nt = 0; nt < 4; nt++) {
                const int Ncol = wn * 32 + nt * 8;
                bfr[nt][0] = Bs[(Ncol + gr) * SAS + kb + gc];
                bfr[nt][1] = Bs[(Ncol + gr) * SAS + kb + gc + 4];
            }
#pragma unroll
            for (int mt = 0; mt < 4; mt++)
#pragma unroll
                for (int nt = 0; nt < 4; nt++)
                    mma_tf32_16x8x8(fr.acc[mt][nt], afr[mt], bfr[nt]);
        }

        if (c + 1 < NCH) {
            const int nxt = cur ^ 1;
            store_tile(bufA[nxt], va);
            store_tile(bufB[nxt], vb);
        }
        __syncthreads();
    }
}

// ---------------------------------------------------------------------------
// QKV projection: grid (24, 64). bx<16 -> Q head bx; [16,20) -> K head bx-16;
// [20,24) -> V head bx-20. m0 = by*128 indexes (b,t).
// ---------------------------------------------------------------------------
__global__ void __launch_bounds__(256)
qkv_gemm_mma_kernel(const float* __restrict__ X,
                    const float* __restrict__ Wq,
                    const float* __restrict__ Wk,
                    const float* __restrict__ Wv)
{
    extern __shared__ uint32_t smem[];
    const int bx = blockIdx.x;
    const int m0 = blockIdx.y * 128;

    const float* Bg;
    if (bx < 16)      Bg = Wq + (size_t)bx * 128 * 2048;
    else if (bx < 20) Bg = Wk + (size_t)(bx - 16) * 128 * 2048;
    else              Bg = Wv + (size_t)(bx - 20) * 128 * 2048;

    Frag fr;
    gemm_mainloop(X + (size_t)m0 * 2048, Bg, smem, fr);

    const int tid = threadIdx.x;
    const int wid = tid >> 5;
    const int lane = tid & 31;
    const int wm = wid & 1;
    const int wn = wid >> 1;
    const int gr = lane >> 2;
    const int gc = lane & 3;

#pragma unroll
    for (int mt = 0; mt < 4; mt++) {
#pragma unroll
        for (int half = 0; half < 2; half++) {
            const int m = m0 + wm * 64 + mt * 16 + gr + half * 8;
            const int bb = m >> 11;
            const int t = m & 2047;
            float* base;
            if (bx < 16)      base = g_q + (((size_t)(bb * 16 + bx)) * 2048 + t) * 128;
            else if (bx < 20) base = g_k + (((size_t)(bb * 4 + bx - 16)) * 2048 + t) * 128;
            else              base = g_v + (((size_t)(bb * 4 + bx - 20)) * 2048 + t) * 128;
#pragma unroll
            for (int nt = 0; nt < 4; nt++) {
                const int col = wn * 32 + nt * 8 + gc * 2;
                *(float2*)(base + col) = make_float2(fr.acc[mt][nt][half * 2],
                                                     fr.acc[mt][nt][half * 2 + 1]);
            }
        }
    }
}

// ---------------------------------------------------------------------------
// Output projection: out[m,n] = sum_k g_attn[m,k] * Wo[n,k].  grid (16, 64)
// ---------------------------------------------------------------------------
__global__ void __launch_bounds__(256)
out_gemm_mma_kernel(const float* __restrict__ Wo, float* __restrict__ out)
{
    extern __shared__ uint32_t smem[];
    const int n0 = blockIdx.x * 128;
    const int m0 = blockIdx.y * 128;

    Frag fr;
    gemm_mainloop(g_attn + (size_t)m0 * 2048, Wo + (size_t)n0 * 2048, smem, fr);

    const int tid = threadIdx.x;
    const int wid = tid >> 5;
    const int lane = tid & 31;
    const int wm = wid & 1;
    const int wn = wid >> 1;
    const int gr = lane >> 2;
    const int gc = lane & 3;

#pragma unroll
    for (int mt = 0; mt < 4; mt++) {
#pragma unroll
        for (int half = 0; half < 2; half++) {
            const int m = m0 + wm * 64 + mt * 16 + gr + half * 8;
            float* base = out + (size_t)m * 2048 + n0;
#pragma unroll
            for (int nt = 0; nt < 4; nt++) {
                const int col = wn * 32 + nt * 8 + gc * 2;
                *(float2*)(base + col) = make_float2(fr.acc[mt][nt][half * 2],
                                                     fr.acc[mt][nt][half * 2 + 1]);
            }
        }
    }
}

// ---------------------------------------------------------------------------
// RoPE (interleaved pairs). H=16 -> g_q (folds 1/sqrt(128)), H=4 -> g_k.
// ---------------------------------------------------------------------------
template <int H, bool SCALE>
__global__ __launch_bounds__(256) void rope_kernel(
    const float* __restrict__ cosT, const float* __restrict__ sinT)
{
    size_t idx = (size_t)blockIdx.x * blockDim.x + threadIdx.x;
    size_t total = (size_t)4 * H * 2048 * 64;
    if (idx >= total) return;
    int i = (int)(idx & 63);
    size_t row = idx >> 6;             // (b*H + h)*2048 + t
    int t = (int)(row & 2047);
    float* ptr = (H == 16 ? g_q : g_k) + row * 128 + i * 2;
    float e = ptr[0], o = ptr[1];
    float c = cosT[t * 64 + i];
    float s = sinT[t * 64 + i];
    float ne = e * c - o * s;
    float no = e * s + o * c;
    if (SCALE) {
        const float sc = 0.08838834764831845f;   // 1/sqrt(128)
        ne *= sc; no *= sc;
    }
    ptr[0] = ne;
    ptr[1] = no;
}

// ---------------------------------------------------------------------------
// Causal flash attention, fp32. 64 q-rows x 64 k-cols per tile, D=128.
// grid (32, 16, 4), 256 threads. Q pre-scaled by 1/sqrt(128).
// ---------------------------------------------------------------------------
#define FD 132
#define SD 68

__global__ __launch_bounds__(256) void flash_attn_kernel()
{
    extern __shared__ float sm[];
    float* Qs  = sm;                 // 64*FD
    float* Ks  = Qs + 64 * FD;       // 64*FD
    float* Vs  = Ks + 64 * FD;       // 64*FD
    float* Ss  = Vs + 64 * FD;       // 64*SD
    float* ms  = Ss + 64 * SD;       // 64
    float* ls  = ms + 64;            // 64
    float* als = ls + 64;            // 64

    const int tid = threadIdx.x;
    const int b = blockIdx.z;
    const int h = blockIdx.y;
    const int qt = blockIdx.x;
    const int q0 = qt * 64;
    const int kvh = h >> 2;

    const float* qptr = g_q + (((size_t)(b * 16 + h) * 2048 + q0) * 128);
    const float* kbase = g_k + ((size_t)(b * 4 + kvh) * 2048) * 128;
    const float* vbase = g_v + ((size_t)(b * 4 + kvh) * 2048) * 128;

#pragma unroll
    for (int u = 0; u < 8; u++) {
        int f = tid + u * 256;
        int r = f >> 5, dv = f & 31;
        *(float4*)&Qs[r * FD + dv * 4] = *(const float4*)(qptr + (size_t)r * 128 + dv * 4);
    }
    if (tid < 64) { ms[tid] = -1e30f; ls[tid] = 0.f; }

    const int ro = tid >> 4;
    const int co = tid & 15;
    float oacc[4][8];
#pragma unroll
    for (int i = 0; i < 4; i++)
#pragma unroll
        for (int c = 0; c < 8; c++) oacc[i][c] = 0.f;

    __syncthreads();

    for (int kt = 0; kt <= qt; kt++) {
        const float* kp = kbase + (size_t)kt * 64 * 128;
        const float* vp = vbase + (size_t)kt * 64 * 128;
#pragma unroll
        for (int u = 0; u < 8; u++) {
            int f = tid + u * 256;
            int r = f >> 5, dv = f & 31;
            *(float4*)&Ks[r * FD + dv * 4] = *(const float4*)(kp + (size_t)r * 128 + dv * 4);
            *(float4*)&Vs[r * FD + dv * 4] = *(const float4*)(vp + (size_t)r * 128 + dv * 4);
        }
        __syncthreads();

        float s[4][4];
#pragma unroll
        for (int i = 0; i < 4; i++)
#pragma unroll
            for (int j = 0; j < 4; j++) s[i][j] = 0.f;

        for (int d4 = 0; d4 < 32; d4++) {
            float4 qv[4], kv[4];
#pragma unroll
            for (int i = 0; i < 4; i++)
                qv[i] = *(const float4*)&Qs[(ro * 4 + i) * FD + d4 * 4];
#pragma unroll
            for (int j = 0; j < 4; j++)
                kv[j] = *(const float4*)&Ks[(co * 4 + j) * FD + d4 * 4];
#pragma unroll
            for (int i = 0; i < 4; i++)
#pragma unroll
                for (int j = 0; j < 4; j++) {
                    s[i][j] = fmaf(qv[i].x, kv[j].x, s[i][j]);
                    s[i][j] = fmaf(qv[i].y, kv[j].y, s[i][j]);
                    s[i][j] = fmaf(qv[i].z, kv[j].z, s[i][j]);
                    s[i][j] = fmaf(qv[i].w, kv[j].w, s[i][j]);
                }
        }

        if (kt == qt) {
#pragma unroll
            for (int i = 0; i < 4; i++)
#pragma unroll
                for (int j = 0; j < 4; j++)
                    if (co * 4 + j > ro * 4 + i) s[i][j] = -1e30f;
        }
#pragma unroll
        for (int i = 0; i < 4; i++)
#pragma unroll
            for (int j = 0; j < 4; j++)
                Ss[(ro * 4 + i) * SD + co * 4 + j] = s[i][j];
        __syncthreads();

        if (tid < 64) {
            int r = tid;
            float mo = ms[r];
            float mn = mo;
#pragma unroll 8
            for (int j = 0; j < 64; j++) mn = fmaxf(mn, Ss[r * SD + j]);
            float al = __expf(mo - mn);
            float sum = 0.f;
#pragma unroll 8
            for (int j = 0; j < 64; j++) {
                float p = __expf(Ss[r * SD + j] - mn);
                Ss[r * SD + j] = p;
                sum += p;
            }
            ls[r] = ls[r] * al + sum;
            ms[r] = mn;
            als[r] = al;
        }
        __syncthreads();

        float al[4];
#pragma unroll
        for (int i = 0; i < 4; i++) al[i] = als[ro * 4 + i];
#pragma unroll
        for (int i = 0; i < 4; i++)
#pragma unroll
            for (int c = 0; c < 8; c++) oacc[i][c] *= al[i];

        for (int j = 0; j < 64; j++) {
            float p[4];
#pragma unroll
            for (int i = 0; i < 4; i++) p[i] = Ss[(ro * 4 + i) * SD + j];
            float4 v0 = *(const float4*)&Vs[j * FD + co * 8];
            float4 v1 = *(const float4*)&Vs[j * FD + co * 8 + 4];
#pragma unroll
            for (int i = 0; i < 4; i++) {
                oacc[i][0] = fmaf(p[i], v0.x, oacc[i][0]);
                oacc[i][1] = fmaf(p[i], v0.y, oacc[i][1]);
                oacc[i][2] = fmaf(p[i], v0.z, oacc[i][2]);
                oacc[i][3] = fmaf(p[i], v0.w, oacc[i][3]);
                oacc[i][4] = fmaf(p[i], v1.x, oacc[i][4]);
                oacc[i][5] = fmaf(p[i], v1.y, oacc[i][5]);
                oacc[i][6] = fmaf(p[i], v1.z, oacc[i][6]);
                oacc[i][7] = fmaf(p[i], v1.w, oacc[i][7]);
            }
        }
        __syncthreads();
    }

#pragma unroll
    for (int i = 0; i < 4; i++) {
        int r = ro * 4 + i;
        float inv = 1.f / ls[r];
        int t = q0 + r;
        float* dst = g_attn + ((size_t)(b * 2048 + t) * 2048) + h * 128 + co * 8;
        float4 o0 = make_float4(oacc[i][0] * inv, oacc[i][1] * inv,
                                oacc[i][2] * inv, oacc[i][3] * inv);
        float4 o1 = make_float4(oacc[i][4] * inv, oacc[i][5] * inv,
                                oacc[i][6] * inv, oacc[i][7] * inv);
        *(float4*)(dst)     = o0;
        *(float4*)(dst + 4) = o1;
    }
}

// ---------------------------------------------------------------------------
extern "C" void kernel_launch(void* const* d_in, const int* in_sizes, int n_in,
                              void* d_out, int out_size)
{
    const float* x    = (const float*)d_in[0];
    const float* wq   = (const float*)d_in[1];
    const float* wk   = (const float*)d_in[2];
    const float* wv   = (const float*)d_in[3];
    const float* wo   = (const float*)d_in[4];
    const float* rc   = (const float*)d_in[5];
    const float* rs   = (const float*)d_in[6];
    float* out = (float*)d_out;

    (void)in_sizes; (void)n_in; (void)out_size;

    cudaFuncSetAttribute(qkv_gemm_mma_kernel,
                         cudaFuncAttributeMaxDynamicSharedMemorySize, GEMM_SMEM_BYTES);
    cudaFuncSetAttribute(out_gemm_mma_kernel,
                         cudaFuncAttributeMaxDynamicSharedMemorySize, GEMM_SMEM_BYTES);

    // 1. Fused QKV projection (mma.sync tf32) -> g_q/g_k/g_v
    qkv_gemm_mma_kernel<<<dim3(24, 64), 256, GEMM_SMEM_BYTES>>>(x, wq, wk, wv);

    // 2. RoPE (Q also gets 1/sqrt(128) folded in)
    rope_kernel<16, true ><<<(4 * 16 * 2048 * 64 + 255) / 256, 256>>>(rc, rs);
    rope_kernel<4,  false><<<(4 * 4  * 2048 * 64 + 255) / 256, 256>>>(rc, rs);

    // 3. Causal flash attention -> g_attn [B,T,C]
    const int fa_smem = (3 * 64 * FD + 64 * SD + 3 * 64) * (int)sizeof(float);
    cudaFuncSetAttribute(flash_attn_kernel,
                         cudaFuncAttributeMaxDynamicSharedMemorySize, fa_smem);
    flash_attn_kernel<<<dim3(32, 16, 4), 256, fa_smem>>>();

    // 4. Output projection (mma.sync tf32) -> d_out
    out_gemm_mma_kernel<<<dim3(16, 64), 256, GEMM_SMEM_BYTES>>>(wo, out);
}

// round 4
// speedup vs baseline: 3.3034x; 2.4424x over previous
#include <cuda_runtime.h>
#include <math.h>
#include <cstdint>

// Problem constants: B=4, T=2048, C=2048, NH=16, NKV=4, HD=128

// Scratch (allocation-free rule: __device__ globals)
__device__ float g_q[(size_t)4 * 16 * 2048 * 128];   // [B,16,T,128] roped+scaled
__device__ float g_k[(size_t)4 * 4 * 2048 * 128];    // [B,4,T,128]  roped
__device__ float g_v[(size_t)4 * 4 * 2048 * 128];    // [B,4,T,128]
__device__ float g_attn[(size_t)4 * 2048 * 2048];    // [B,T,C]

// ===========================================================================
// mma.sync tf32 helpers (plain sm_80+ PTX -- valid for non-'a' sm_103 target)
// ===========================================================================
__device__ __forceinline__ uint32_t f2tf32(float v) {
    uint32_t r;
    asm("cvt.rna.tf32.f32 %0, %1;" : "=r"(r) : "f"(v));
    return r;
}

__device__ __forceinline__ void mma_tf32_16x8x8(float* c, const uint32_t* a,
                                                const uint32_t* b) {
    asm volatile(
        "mma.sync.aligned.m16n8k8.row.col.f32.tf32.tf32.f32 "
        "{%0,%1,%2,%3}, {%4,%5,%6,%7}, {%8,%9}, {%0,%1,%2,%3};"
        : "+f"(c[0]), "+f"(c[1]), "+f"(c[2]), "+f"(c[3])
        : "r"(a[0]), "r"(a[1]), "r"(a[2]), "r"(a[3]), "r"(b[0]), "r"(b[1]));
}

// ===========================================================================
// tf32 GEMM mainloop (from R3): 128x128 tile of C = A * B^T, K=2048.
// 256 threads (8 warps), warp = 64x32 subtile, BK=32 double buffered.
// ===========================================================================
#define SAS 36
#define TILE_WORDS (128 * SAS)
#define GEMM_SMEM_BYTES (4 * TILE_WORDS * 4)
#define NCH 64

struct Frag { float acc[4][4][4]; };   // [mt][nt][4]

__device__ __forceinline__ void store_tile(uint32_t* dst, const float4* v) {
    const int tid = threadIdx.x;
#pragma unroll
    for (int u = 0; u < 4; u++) {
        int f = tid + u * 256;
        int row = f >> 3;
        int c4 = f & 7;
        uint4 w;
        w.x = f2tf32(v[u].x); w.y = f2tf32(v[u].y);
        w.z = f2tf32(v[u].z); w.w = f2tf32(v[u].w);
        *(uint4*)(dst + row * SAS + c4 * 4) = w;
    }
}

__device__ __forceinline__ void load_global(float4* v, const float* __restrict__ src) {
    const int tid = threadIdx.x;
#pragma unroll
    for (int u = 0; u < 4; u++) {
        int f = tid + u * 256;
        int row = f >> 3;
        int c4 = f & 7;
        v[u] = *(const float4*)(src + (size_t)row * 2048 + c4 * 4);
    }
}

__device__ __forceinline__ void gemm_mainloop(const float* __restrict__ Ag,
                                              const float* __restrict__ Bg,
                                              uint32_t* smem, Frag& fr)
{
    const int tid = threadIdx.x;
    const int wid = tid >> 5;
    const int lane = tid & 31;
    const int wm = wid & 1;
    const int wn = wid >> 1;
    const int gr = lane >> 2;
    const int gc = lane & 3;

    uint32_t* bufA[2] = { smem, smem + 2 * TILE_WORDS };
    uint32_t* bufB[2] = { smem + TILE_WORDS, smem + 3 * TILE_WORDS };

#pragma unroll
    for (int mt = 0; mt < 4; mt++)
#pragma unroll
        for (int nt = 0; nt < 4; nt++)
#pragma unroll
            for (int i = 0; i < 4; i++) fr.acc[mt][nt][i] = 0.f;

    {
        float4 va[4], vb[4];
        load_global(va, Ag);
        load_global(vb, Bg);
        store_tile(bufA[0], va);
        store_tile(bufB[0], vb);
    }
    __syncthreads();

    for (int c = 0; c < NCH; c++) {
        const int cur = c & 1;
        float4 va[4], vb[4];
        if (c + 1 < NCH) {
            load_global(va, Ag + (c + 1) * 32);
            load_global(vb, Bg + (c + 1) * 32);
        }
        const uint32_t* As = bufA[cur];
        const uint32_t* Bs = bufB[cur];
#pragma unroll
        for (int ks = 0; ks < 4; ks++) {
            const int kb = ks * 8;
            uint32_t afr[4][4];
            uint32_t bfr[4][2];
#pragma unroll
            for (int mt = 0; mt < 4; mt++) {
                const int R = wm * 64 + mt * 16;
                afr[mt][0] = As[(R + gr) * SAS + kb + gc];
                afr[mt][1] = As[(R + gr + 8) * SAS + kb + gc];
                afr[mt][2] = As[(R + gr) * SAS + kb + gc + 4];
                afr[mt][3] = As[(R + gr + 8) * SAS + kb + gc + 4];
            }
#pragma unroll
            for (int nt = 0; nt < 4; nt++) {
                const int Ncol = wn * 32 + nt * 8;
                bfr[nt][0] = Bs[(Ncol + gr) * SAS + kb + gc];
                bfr[nt][1] = Bs[(Ncol + gr) * SAS + kb + gc + 4];
            }
#pragma unroll
            for (int mt = 0; mt < 4; mt++)
#pragma unroll
                for (int nt = 0; nt < 4; nt++)
                    mma_tf32_16x8x8(fr.acc[mt][nt], afr[mt], bfr[nt]);
        }
        if (c + 1 < NCH) {
            const int nxt = cur ^ 1;
            store_tile(bufA[nxt], va);
            store_tile(bufB[nxt], vb);
        }
        __syncthreads();
    }
}

// ---------------------------------------------------------------------------
// QKV projection with fused RoPE. grid (24, 64).
// bx<16 -> Q head bx (rope + 1/sqrt(128)); [16,20) -> K head bx-16 (rope);
// [20,24) -> V head bx-20 (plain).
// ---------------------------------------------------------------------------
__global__ void __launch_bounds__(256)
qkv_gemm_mma_kernel(const float* __restrict__ X,
                    const float* __restrict__ Wq,
                    const float* __restrict__ Wk,
                    const float* __restrict__ Wv,
                    const float* __restrict__ rc,
                    const float* __restrict__ rs)
{
    extern __shared__ uint32_t smem[];
    const int bx = blockIdx.x;
    const int m0 = blockIdx.y * 128;

    const float* Bg;
    if (bx < 16)      Bg = Wq + (size_t)bx * 128 * 2048;
    else if (bx < 20) Bg = Wk + (size_t)(bx - 16) * 128 * 2048;
    else              Bg = Wv + (size_t)(bx - 20) * 128 * 2048;

    Frag fr;
    gemm_mainloop(X + (size_t)m0 * 2048, Bg, smem, fr);

    const int tid = threadIdx.x;
    const int wid = tid >> 5;
    const int lane = tid & 31;
    const int wm = wid & 1;
    const int wn = wid >> 1;
    const int gr = lane >> 2;
    const int gc = lane & 3;
    const int mode = (bx < 16) ? 0 : (bx < 20 ? 1 : 2);   // 0=Q,1=K,2=V

#pragma unroll
    for (int mt = 0; mt < 4; mt++) {
#pragma unroll
        for (int half = 0; half < 2; half++) {
            const int m = m0 + wm * 64 + mt * 16 + gr + half * 8;
            const int bb = m >> 11;
            const int t = m & 2047;
            float* base;
            if (mode == 0)      base = g_q + (((size_t)(bb * 16 + bx)) * 2048 + t) * 128;
            else if (mode == 1) base = g_k + (((size_t)(bb * 4 + bx - 16)) * 2048 + t) * 128;
            else                base = g_v + (((size_t)(bb * 4 + bx - 20)) * 2048 + t) * 128;
#pragma unroll
            for (int nt = 0; nt < 4; nt++) {
                const int col = wn * 32 + nt * 8 + gc * 2;   // even; pair (col,col+1)
                float e = fr.acc[mt][nt][half * 2];
                float o = fr.acc[mt][nt][half * 2 + 1];
                if (mode < 2) {
                    const int i = col >> 1;                  // rope pair idx 0..63
                    float cc = rc[t * 64 + i];
                    float ss = rs[t * 64 + i];
                    float ne = e * cc - o * ss;
                    float no = e * ss + o * cc;
                    if (mode == 0) {
                        const float sc = 0.08838834764831845f;  // 1/sqrt(128)
                        ne *= sc; no *= sc;
                    }
                    e = ne; o = no;
                }
                *(float2*)(base + col) = make_float2(e, o);
            }
        }
    }
}

// ---------------------------------------------------------------------------
// Output projection: out[m,n] = sum_k g_attn[m,k] * Wo[n,k].  grid (16, 64)
// ---------------------------------------------------------------------------
__global__ void __launch_bounds__(256)
out_gemm_mma_kernel(const float* __restrict__ Wo, float* __restrict__ out)
{
    extern __shared__ uint32_t smem[];
    const int n0 = blockIdx.x * 128;
    const int m0 = blockIdx.y * 128;

    Frag fr;
    gemm_mainloop(g_attn + (size_t)m0 * 2048, Wo + (size_t)n0 * 2048, smem, fr);

    const int tid = threadIdx.x;
    const int wid = tid >> 5;
    const int lane = tid & 31;
    const int wm = wid & 1;
    const int wn = wid >> 1;
    const int gr = lane >> 2;
    const int gc = lane & 3;

#pragma unroll
    for (int mt = 0; mt < 4; mt++) {
#pragma unroll
        for (int half = 0; half < 2; half++) {
            const int m = m0 + wm * 64 + mt * 16 + gr + half * 8;
            float* base = out + (size_t)m * 2048 + n0;
#pragma unroll
            for (int nt = 0; nt < 4; nt++) {
                const int col = wn * 32 + nt * 8 + gc * 2;
                *(float2*)(base + col) = make_float2(fr.acc[mt][nt][half * 2],
                                                     fr.acc[mt][nt][half * 2 + 1]);
            }
        }
    }
}

// ===========================================================================
// Flash attention with mma.sync tf32.
// 128 threads (4 warps), BM=64 q rows, BN=64 kv cols, D=128.
// grid (32, 16, 4). Q pre-scaled by 1/sqrt(128), roped. Causal.
// Warp w owns q rows [16w, 16w+16). Q A-fragments persistent in registers.
// SMEM: Ks[64][132] (tf32), Vs[64][136] (tf32), Ps[64][68] (tf32 P values).
// ===========================================================================
#define KP 132
#define VP 136
#define PP 68
#define FA_SMEM_BYTES ((64 * KP + 64 * VP + 64 * PP) * 4)

__global__ void __launch_bounds__(128)
flash_attn_mma_kernel()
{
    extern __shared__ uint32_t fsm[];
    uint32_t* Ks = fsm;                  // [kv][d] pad KP
    uint32_t* Vs = Ks + 64 * KP;         // [kv][d] pad VP
    uint32_t* Ps = Vs + 64 * VP;         // [qrow][kv] pad PP

    const int tid = threadIdx.x;
    const int wid = tid >> 5;            // 0..3
    const int lane = tid & 31;
    const int gr = lane >> 2;            // 0..7
    const int gc = lane & 3;             // 0..3

    const int b = blockIdx.z;
    const int h = blockIdx.y;
    const int qt = blockIdx.x;           // 0..31
    const int q0 = qt * 64;
    const int kvh = h >> 2;

    const float* qbase = g_q + (((size_t)(b * 16 + h) * 2048 + q0) * 128);
    const float* kbase = g_k + ((size_t)(b * 4 + kvh) * 2048) * 128;
    const float* vbase = g_v + ((size_t)(b * 4 + kvh) * 2048) * 128;

    const int r0 = wid * 16 + gr;        // warp-local q row (this thread's row A)

    // Persistent Q fragments: 16 ksteps x 4 regs
    uint32_t qf[16][4];
#pragma unroll
    for (int ks = 0; ks < 16; ks++) {
        const int kk = ks * 8;
        qf[ks][0] = f2tf32(qbase[(size_t)(r0)     * 128 + kk + gc]);
        qf[ks][1] = f2tf32(qbase[(size_t)(r0 + 8) * 128 + kk + gc]);
        qf[ks][2] = f2tf32(qbase[(size_t)(r0)     * 128 + kk + gc + 4]);
        qf[ks][3] = f2tf32(qbase[(size_t)(r0 + 8) * 128 + kk + gc + 4]);
    }

    float oacc[16][4];
#pragma unroll
    for (int nt = 0; nt < 16; nt++)
#pragma unroll
        for (int i = 0; i < 4; i++) oacc[nt][i] = 0.f;

    float m0v = -1e30f, m1v = -1e30f;    // row maxima (rows r0, r0+8)
    float l0 = 0.f, l1 = 0.f;            // row sums

    for (int kt = 0; kt <= qt; kt++) {
        // ---- load K/V tile (64x128 fp32 -> tf32 smem) ----
        const float* kp_ = kbase + (size_t)kt * 64 * 128;
        const float* vp_ = vbase + (size_t)kt * 64 * 128;
#pragma unroll
        for (int u = 0; u < 16; u++) {
            int f = tid + u * 128;       // 0..2047 (float4 units)
            int row = f >> 5;
            int c4 = f & 31;
            float4 kv4 = *(const float4*)(kp_ + (size_t)row * 128 + c4 * 4);
            float4 vv4 = *(const float4*)(vp_ + (size_t)row * 128 + c4 * 4);
            uint4 kw, vw;
            kw.x = f2tf32(kv4.x); kw.y = f2tf32(kv4.y);
            kw.z = f2tf32(kv4.z); kw.w = f2tf32(kv4.w);
            vw.x = f2tf32(vv4.x); vw.y = f2tf32(vv4.y);
            vw.z = f2tf32(vv4.z); vw.w = f2tf32(vv4.w);
            *(uint4*)(Ks + row * KP + c4 * 4) = kw;
            *(uint4*)(Vs + row * VP + c4 * 4) = vw;
        }
        __syncthreads();

        // ---- S = Q K^T (16 rows x 64 cols per warp) ----
        float sacc[8][4];
#pragma unroll
        for (int nt = 0; nt < 8; nt++)
#pragma unroll
            for (int i = 0; i < 4; i++) sacc[nt][i] = 0.f;

#pragma unroll
        for (int ks = 0; ks < 16; ks++) {
            const int kk = ks * 8;
#pragma unroll
            for (int nt = 0; nt < 8; nt++) {
                uint32_t bf[2];
                bf[0] = Ks[(nt * 8 + gr) * KP + kk + gc];
                bf[1] = Ks[(nt * 8 + gr) * KP + kk + gc + 4];
                mma_tf32_16x8x8(sacc[nt], qf[ks], bf);
            }
        }

        // ---- causal mask on diagonal tile ----
        if (kt == qt) {
#pragma unroll
            for (int nt = 0; nt < 8; nt++) {
#pragma unroll
                for (int i = 0; i < 4; i++) {
                    const int row = r0 + (i >= 2 ? 8 : 0);
                    const int col = nt * 8 + gc * 2 + (i & 1);
                    if (col > row) sacc[nt][i] = -1e30f;
                }
            }
        }

        // ---- online softmax (register + quad shuffle) ----
        float mx0 = -1e30f, mx1 = -1e30f;
#pragma unroll
        for (int nt = 0; nt < 8; nt++) {
            mx0 = fmaxf(mx0, fmaxf(sacc[nt][0], sacc[nt][1]));
            mx1 = fmaxf(mx1, fmaxf(sacc[nt][2], sacc[nt][3]));
        }
        mx0 = fmaxf(mx0, __shfl_xor_sync(0xffffffffu, mx0, 1));
        mx0 = fmaxf(mx0, __shfl_xor_sync(0xffffffffu, mx0, 2));
        mx1 = fmaxf(mx1, __shfl_xor_sync(0xffffffffu, mx1, 1));
        mx1 = fmaxf(mx1, __shfl_xor_sync(0xffffffffu, mx1, 2));

        const float mn0 = fmaxf(m0v, mx0);
        const float mn1 = fmaxf(m1v, mx1);
        const float al0 = __expf(m0v - mn0);
        const float al1 = __expf(m1v - mn1);

        float sum0 = 0.f, sum1 = 0.f;
#pragma unroll
        for (int nt = 0; nt < 8; nt++) {
            float p0 = __expf(sacc[nt][0] - mn0);
            float p1 = __expf(sacc[nt][1] - mn0);
            float p2 = __expf(sacc[nt][2] - mn1);
            float p3 = __expf(sacc[nt][3] - mn1);
            sum0 += p0 + p1;
            sum1 += p2 + p3;
            const int col = nt * 8 + gc * 2;
            Ps[(r0)     * PP + col]     = f2tf32(p0);
            Ps[(r0)     * PP + col + 1] = f2tf32(p1);
            Ps[(r0 + 8) * PP + col]     = f2tf32(p2);
            Ps[(r0 + 8) * PP + col + 1] = f2tf32(p3);
        }
        sum0 += __shfl_xor_sync(0xffffffffu, sum0, 1);
        sum0 += __shfl_xor_sync(0xffffffffu, sum0, 2);
        sum1 += __shfl_xor_sync(0xffffffffu, sum1, 1);
        sum1 += __shfl_xor_sync(0xffffffffu, sum1, 2);

        l0 = l0 * al0 + sum0;
        l1 = l1 * al1 + sum1;
        m0v = mn0;
        m1v = mn1;

        // rescale O
#pragma unroll
        for (int nt = 0; nt < 16; nt++) {
            oacc[nt][0] *= al0; oacc[nt][1] *= al0;
            oacc[nt][2] *= al1; oacc[nt][3] *= al1;
        }
        __syncwarp();   // order P stores before P loads (warp-private region)

        // ---- O += P V ----
#pragma unroll
        for (int ks2 = 0; ks2 < 8; ks2++) {
            const int kk = ks2 * 8;
            uint32_t af[4];
            af[0] = Ps[(r0)     * PP + kk + gc];
            af[1] = Ps[(r0 + 8) * PP + kk + gc];
            af[2] = Ps[(r0)     * PP + kk + gc + 4];
            af[3] = Ps[(r0 + 8) * PP + kk + gc + 4];
#pragma unroll
            for (int nt = 0; nt < 16; nt++) {
                uint32_t bf[2];
                bf[0] = Vs[(kk + gc) * VP + nt * 8 + gr];
                bf[1] = Vs[(kk + gc + 4) * VP + nt * 8 + gr];
                mma_tf32_16x8x8(oacc[nt], af, bf);
            }
        }
        __syncthreads();   // protect Ks/Vs before next tile's overwrite
    }

    // ---- epilogue: normalize + store to g_attn [B,T,C] ----
    const float inv0 = 1.f / l0;
    const float inv1 = 1.f / l1;
    const int t0 = q0 + r0;
    float* dst0 = g_attn + ((size_t)(b * 2048 + t0) * 2048) + h * 128;
    float* dst1 = g_attn + ((size_t)(b * 2048 + t0 + 8) * 2048) + h * 128;
#pragma unroll
    for (int nt = 0; nt < 16; nt++) {
        const int col = nt * 8 + gc * 2;
        *(float2*)(dst0 + col) = make_float2(oacc[nt][0] * inv0, oacc[nt][1] * inv0);
        *(float2*)(dst1 + col) = make_float2(oacc[nt][2] * inv1, oacc[nt][3] * inv1);
    }
}

// ---------------------------------------------------------------------------
extern "C" void kernel_launch(void* const* d_in, const int* in_sizes, int n_in,
                              void* d_out, int out_size)
{
    const float* x    = (const float*)d_in[0];
    const float* wq   = (const float*)d_in[1];
    const float* wk   = (const float*)d_in[2];
    const float* wv   = (const float*)d_in[3];
    const float* wo   = (const float*)d_in[4];
    const float* rc   = (const float*)d_in[5];
    const float* rs   = (const float*)d_in[6];
    float* out = (float*)d_out;

    (void)in_sizes; (void)n_in; (void)out_size;

    cudaFuncSetAttribute(qkv_gemm_mma_kernel,
                         cudaFuncAttributeMaxDynamicSharedMemorySize, GEMM_SMEM_BYTES);
    cudaFuncSetAttribute(out_gemm_mma_kernel,
                         cudaFuncAttributeMaxDynamicSharedMemorySize, GEMM_SMEM_BYTES);
    cudaFuncSetAttribute(flash_attn_mma_kernel,
                         cudaFuncAttributeMaxDynamicSharedMemorySize, FA_SMEM_BYTES);

    // 1. Fused QKV projection + RoPE (mma.sync tf32) -> g_q/g_k/g_v
    qkv_gemm_mma_kernel<<<dim3(24, 64), 256, GEMM_SMEM_BYTES>>>(x, wq, wk, wv, rc, rs);

    // 2. Causal flash attention (mma.sync tf32) -> g_attn [B,T,C]
    flash_attn_mma_kernel<<<dim3(32, 16, 4), 128, FA_SMEM_BYTES>>>();

    // 3. Output projection (mma.sync tf32) -> d_out
    out_gemm_mma_kernel<<<dim3(16, 64), 256, GEMM_SMEM_BYTES>>>(wo, out);
}

// round 5
// speedup vs baseline: 4.5474x; 1.3766x over previous
#include <cuda_runtime.h>
#include <math.h>
#include <cstdint>

// Problem constants: B=4, T=2048, C=2048, NH=16, NKV=4, HD=128

// Scratch (allocation-free rule: __device__ globals)
__device__ float g_q[(size_t)4 * 16 * 2048 * 128];   // [B,16,T,128] roped+scaled, tf32-rounded
__device__ float g_k[(size_t)4 * 4 * 2048 * 128];    // [B,4,T,128]  roped, tf32-rounded
__device__ float g_v[(size_t)4 * 4 * 2048 * 128];    // [B,4,T,128]  tf32-rounded
__device__ float g_attn[(size_t)4 * 2048 * 2048];    // [B,T,C] tf32-rounded
// tf32-rounded copies of inputs (so cp.async + implicit mma truncation is exact)
__device__ float g_xr[(size_t)4 * 2048 * 2048];
__device__ float g_wqr[(size_t)2048 * 2048];
__device__ float g_wkr[(size_t)512 * 2048];
__device__ float g_wvr[(size_t)512 * 2048];
__device__ float g_wor[(size_t)2048 * 2048];

// ===========================================================================
// Helpers (plain sm_80+ PTX -- valid for non-'a' sm_103 target)
// ===========================================================================
__device__ __forceinline__ uint32_t smem_u32(const void* p) {
    uint32_t a;
    asm("{ .reg .u64 t; cvta.to.shared.u64 t, %1; cvt.u32.u64 %0, t; }"
        : "=r"(a) : "l"(p));
    return a;
}
__device__ __forceinline__ uint32_t f2tf32(float v) {
    uint32_t r;
    asm("cvt.rna.tf32.f32 %0, %1;" : "=r"(r) : "f"(v));
    return r;
}
__device__ __forceinline__ float roundtf(float v) {
    return __uint_as_float(f2tf32(v));
}
__device__ __forceinline__ void mma_tf32_16x8x8(float* c, const uint32_t* a,
                                                const uint32_t* b) {
    asm volatile(
        "mma.sync.aligned.m16n8k8.row.col.f32.tf32.tf32.f32 "
        "{%0,%1,%2,%3}, {%4,%5,%6,%7}, {%8,%9}, {%0,%1,%2,%3};"
        : "+f"(c[0]), "+f"(c[1]), "+f"(c[2]), "+f"(c[3])
        : "r"(a[0]), "r"(a[1]), "r"(a[2]), "r"(a[3]), "r"(b[0]), "r"(b[1]));
}
#define CP_ASYNC16(dst, src) \
    asm volatile("cp.async.cg.shared.global [%0], [%1], 16;" :: "r"(dst), "l"(src))
#define CP_COMMIT() asm volatile("cp.async.commit_group;" ::: "memory")
#define CP_WAIT(n)  asm volatile("cp.async.wait_group %0;" :: "n"(n) : "memory")

// ===========================================================================
// Pre-round kernel: dst[i] = tf32_round(src[i]), float4 vectorized.
// ===========================================================================
__global__ void __launch_bounds__(256)
round_tf32_kernel(const float4* __restrict__ src, float4* __restrict__ dst, int n4)
{
    int i = blockIdx.x * blockDim.x + threadIdx.x;
    if (i < n4) {
        float4 v = src[i];
        v.x = roundtf(v.x); v.y = roundtf(v.y);
        v.z = roundtf(v.z); v.w = roundtf(v.w);
        dst[i] = v;
    }
}

// ===========================================================================
// tf32 GEMM mainloop: 128x128 tile of C = A * B^T, K=2048, operands already
// tf32-rounded in global. 256 threads (8 warps), warp = 64x32 subtile.
// BK=32, 3-stage cp.async pipeline. SMEM: 3 stages x (A+B) x 128x36 words.
// ===========================================================================
#define SAS 36
#define TILE_WORDS (128 * SAS)
#define STG 3
#define GEMM_SMEM_BYTES (STG * 2 * TILE_WORDS * 4)   // 110592
#define NCH 64

struct Frag { float acc[4][4][4]; };

__device__ __forceinline__ void gemm_issue(uint32_t sbase, int stage,
                                           const float* __restrict__ Ag,
                                           const float* __restrict__ Bg, int c)
{
    const int tid = threadIdx.x;
    const uint32_t sA = sbase + stage * (2 * TILE_WORDS * 4);
    const uint32_t sB = sA + TILE_WORDS * 4;
    const float* a = Ag + c * 32;
    const float* b = Bg + c * 32;
#pragma unroll
    for (int u = 0; u < 4; u++) {
        int f = tid + u * 256;
        int row = f >> 3;
        int c4 = f & 7;
        CP_ASYNC16(sA + (row * SAS + c4 * 4) * 4, a + (size_t)row * 2048 + c4 * 4);
        CP_ASYNC16(sB + (row * SAS + c4 * 4) * 4, b + (size_t)row * 2048 + c4 * 4);
    }
}

__device__ __forceinline__ void gemm_mainloop(const float* __restrict__ Ag,
                                              const float* __restrict__ Bg,
                                              uint32_t* smem, Frag& fr)
{
    const int tid = threadIdx.x;
    const int wid = tid >> 5;
    const int lane = tid & 31;
    const int wm = wid & 1;
    const int wn = wid >> 1;
    const int gr = lane >> 2;
    const int gc = lane & 3;
    const uint32_t sbase = smem_u32(smem);

#pragma unroll
    for (int mt = 0; mt < 4; mt++)
#pragma unroll
        for (int nt = 0; nt < 4; nt++)
#pragma unroll
            for (int i = 0; i < 4; i++) fr.acc[mt][nt][i] = 0.f;

    gemm_issue(sbase, 0, Ag, Bg, 0); CP_COMMIT();
    gemm_issue(sbase, 1, Ag, Bg, 1); CP_COMMIT();

    for (int c = 0; c < NCH; c++) {
        if (c + 2 < NCH) gemm_issue(sbase, (c + 2) % STG, Ag, Bg, c + 2);
        CP_COMMIT();      // always commit (possibly empty) -> uniform wait count
        CP_WAIT(2);       // stage c complete
        __syncthreads();

        const uint32_t* As = smem + (c % STG) * 2 * TILE_WORDS;
        const uint32_t* Bs = As + TILE_WORDS;
#pragma unroll
        for (int ks = 0; ks < 4; ks++) {
            const int kb = ks * 8;
            uint32_t afr[4][4];
            uint32_t bfr[4][2];
#pragma unroll
            for (int mt = 0; mt < 4; mt++) {
                const int R = wm * 64 + mt * 16;
                afr[mt][0] = As[(R + gr) * SAS + kb + gc];
                afr[mt][1] = As[(R + gr + 8) * SAS + kb + gc];
                afr[mt][2] = As[(R + gr) * SAS + kb + gc + 4];
                afr[mt][3] = As[(R + gr + 8) * SAS + kb + gc + 4];
            }
#pragma unroll
            for (int nt = 0; nt < 4; nt++) {
                const int Ncol = wn * 32 + nt * 8;
                bfr[nt][0] = Bs[(Ncol + gr) * SAS + kb + gc];
                bfr[nt][1] = Bs[(Ncol + gr) * SAS + kb + gc + 4];
            }
#pragma unroll
            for (int mt = 0; mt < 4; mt++)
#pragma unroll
                for (int nt = 0; nt < 4; nt++)
                    mma_tf32_16x8x8(fr.acc[mt][nt], afr[mt], bfr[nt]);
        }
        __syncthreads();   // all warps done reading before stage reuse
    }
}

// ---------------------------------------------------------------------------
// QKV projection with fused RoPE. grid (24, 64). Outputs tf32-rounded.
// ---------------------------------------------------------------------------
__global__ void __launch_bounds__(256)
qkv_gemm_mma_kernel(const float* __restrict__ rc, const float* __restrict__ rs)
{
    extern __shared__ uint32_t smem[];
    const int bx = blockIdx.x;
    const int m0 = blockIdx.y * 128;

    const float* Bg;
    if (bx < 16)      Bg = g_wqr + (size_t)bx * 128 * 2048;
    else if (bx < 20) Bg = g_wkr + (size_t)(bx - 16) * 128 * 2048;
    else              Bg = g_wvr + (size_t)(bx - 20) * 128 * 2048;

    Frag fr;
    gemm_mainloop(g_xr + (size_t)m0 * 2048, Bg, smem, fr);

    const int tid = threadIdx.x;
    const int wid = tid >> 5;
    const int lane = tid & 31;
    const int wm = wid & 1;
    const int wn = wid >> 1;
    const int gr = lane >> 2;
    const int gc = lane & 3;
    const int mode = (bx < 16) ? 0 : (bx < 20 ? 1 : 2);   // 0=Q,1=K,2=V

#pragma unroll
    for (int mt = 0; mt < 4; mt++) {
#pragma unroll
        for (int half = 0; half < 2; half++) {
            const int m = m0 + wm * 64 + mt * 16 + gr + half * 8;
            const int bb = m >> 11;
            const int t = m & 2047;
            float* base;
            if (mode == 0)      base = g_q + (((size_t)(bb * 16 + bx)) * 2048 + t) * 128;
            else if (mode == 1) base = g_k + (((size_t)(bb * 4 + bx - 16)) * 2048 + t) * 128;
            else                base = g_v + (((size_t)(bb * 4 + bx - 20)) * 2048 + t) * 128;
#pragma unroll
            for (int nt = 0; nt < 4; nt++) {
                const int col = wn * 32 + nt * 8 + gc * 2;
                float e = fr.acc[mt][nt][half * 2];
                float o = fr.acc[mt][nt][half * 2 + 1];
                if (mode < 2) {
                    const int i = col >> 1;
                    float cc = rc[t * 64 + i];
                    float ss = rs[t * 64 + i];
                    float ne = e * cc - o * ss;
                    float no = e * ss + o * cc;
                    if (mode == 0) {
                        const float sc = 0.08838834764831845f;  // 1/sqrt(128)
                        ne *= sc; no *= sc;
                    }
                    e = ne; o = no;
                }
                *(float2*)(base + col) = make_float2(roundtf(e), roundtf(o));
            }
        }
    }
}

// ---------------------------------------------------------------------------
// Output projection: out[m,n] = sum_k g_attn[m,k] * Wo[n,k].  grid (16, 64)
// ---------------------------------------------------------------------------
__global__ void __launch_bounds__(256)
out_gemm_mma_kernel(float* __restrict__ out)
{
    extern __shared__ uint32_t smem[];
    const int n0 = blockIdx.x * 128;
    const int m0 = blockIdx.y * 128;

    Frag fr;
    gemm_mainloop(g_attn + (size_t)m0 * 2048, g_wor + (size_t)n0 * 2048, smem, fr);

    const int tid = threadIdx.x;
    const int wid = tid >> 5;
    const int lane = tid & 31;
    const int wm = wid & 1;
    const int wn = wid >> 1;
    const int gr = lane >> 2;
    const int gc = lane & 3;

#pragma unroll
    for (int mt = 0; mt < 4; mt++) {
#pragma unroll
        for (int half = 0; half < 2; half++) {
            const int m = m0 + wm * 64 + mt * 16 + gr + half * 8;
            float* base = out + (size_t)m * 2048 + n0;
#pragma unroll
            for (int nt = 0; nt < 4; nt++) {
                const int col = wn * 32 + nt * 8 + gc * 2;
                *(float2*)(base + col) = make_float2(fr.acc[mt][nt][half * 2],
                                                     fr.acc[mt][nt][half * 2 + 1]);
            }
        }
    }
}

// ===========================================================================
// Flash attention, mma.sync tf32, 256 threads (8 warps).
// BM=128 q rows per CTA, BN=64 kv cols per tile, D=128. grid (16, 16, 4).
// Q/K/V already tf32-rounded (Q roped+scaled, K roped). Causal.
// Warp w owns q rows [16w, 16w+16). Q frags persistent in registers.
// SMEM: 2 stages x (Ks[64][132] + Vs[64][136]) + Ps[128][68]. cp.async.
// ===========================================================================
#define KP 132
#define VP 136
#define PP 68
#define FA_STAGE_WORDS (64 * KP + 64 * VP)
#define FA_SMEM_BYTES ((2 * FA_STAGE_WORDS + 128 * PP) * 4)   // 172160

__device__ __forceinline__ void fa_issue_kv(uint32_t stage_addr,
                                            const float* __restrict__ kbase,
                                            const float* __restrict__ vbase, int kt)
{
    const int tid = threadIdx.x;
    const float* kp = kbase + (size_t)kt * 64 * 128;
    const float* vp = vbase + (size_t)kt * 64 * 128;
#pragma unroll
    for (int u = 0; u < 8; u++) {
        int f = tid + u * 256;          // 0..2047 float4 slots
        int row = f >> 5;
        int c4 = f & 31;
        CP_ASYNC16(stage_addr + (row * KP + c4 * 4) * 4,
                   kp + (size_t)row * 128 + c4 * 4);
        CP_ASYNC16(stage_addr + 64 * KP * 4 + (row * VP + c4 * 4) * 4,
                   vp + (size_t)row * 128 + c4 * 4);
    }
}

__global__ void __launch_bounds__(256)
flash_attn_mma_kernel()
{
    extern __shared__ uint32_t fsm[];
    uint32_t* Ps = fsm + 2 * FA_STAGE_WORDS;   // [qrow 0..127][kv] pad PP

    const int tid = threadIdx.x;
    const int wid = tid >> 5;            // 0..7
    const int lane = tid & 31;
    const int gr = lane >> 2;
    const int gc = lane & 3;

    const int b = blockIdx.z;
    const int h = blockIdx.y;
    const int qt = blockIdx.x;           // 0..15 (128-row q tiles)
    const int q0 = qt * 128;
    const int kvh = h >> 2;

    const float* qbase = g_q + (((size_t)(b * 16 + h) * 2048 + q0) * 128);
    const float* kbase = g_k + ((size_t)(b * 4 + kvh) * 2048) * 128;
    const float* vbase = g_v + ((size_t)(b * 4 + kvh) * 2048) * 128;

    const int r0 = wid * 16 + gr;        // CTA-local q row

    // Persistent Q fragments (values already tf32-representable -> raw bits)
    uint32_t qf[16][4];
#pragma unroll
    for (int ks = 0; ks < 16; ks++) {
        const int kk = ks * 8;
        qf[ks][0] = __float_as_uint(qbase[(size_t)(r0)     * 128 + kk + gc]);
        qf[ks][1] = __float_as_uint(qbase[(size_t)(r0 + 8) * 128 + kk + gc]);
        qf[ks][2] = __float_as_uint(qbase[(size_t)(r0)     * 128 + kk + gc + 4]);
        qf[ks][3] = __float_as_uint(qbase[(size_t)(r0 + 8) * 128 + kk + gc + 4]);
    }

    float oacc[16][4];
#pragma unroll
    for (int nt = 0; nt < 16; nt++)
#pragma unroll
        for (int i = 0; i < 4; i++) oacc[nt][i] = 0.f;

    float m0v = -1e30f, m1v = -1e30f;
    float l0 = 0.f, l1 = 0.f;

    const uint32_t sb = smem_u32(fsm);
    const int ntiles = 2 * qt + 2;

    fa_issue_kv(sb, kbase, vbase, 0);
    CP_COMMIT();

    for (int kt = 0; kt < ntiles; kt++) {
        if (kt + 1 < ntiles)
            fa_issue_kv(sb + ((kt + 1) & 1) * FA_STAGE_WORDS * 4, kbase, vbase, kt + 1);
        CP_COMMIT();      // always (possibly empty)
        CP_WAIT(1);       // tile kt complete
        __syncthreads();

        const uint32_t* Ks = fsm + (kt & 1) * FA_STAGE_WORDS;
        const uint32_t* Vs = Ks + 64 * KP;

        // ---- S = Q K^T (16 rows x 64 cols per warp) ----
        float sacc[8][4];
#pragma unroll
        for (int nt = 0; nt < 8; nt++)
#pragma unroll
            for (int i = 0; i < 4; i++) sacc[nt][i] = 0.f;

#pragma unroll
        for (int ks = 0; ks < 16; ks++) {
            const int kk = ks * 8;
#pragma unroll
            for (int nt = 0; nt < 8; nt++) {
                uint32_t bf[2];
                bf[0] = Ks[(nt * 8 + gr) * KP + kk + gc];
                bf[1] = Ks[(nt * 8 + gr) * KP + kk + gc + 4];
                mma_tf32_16x8x8(sacc[nt], qf[ks], bf);
            }
        }

        // ---- causal mask (only last two tiles can intersect the diagonal) ----
        if (kt >= 2 * qt) {
#pragma unroll
            for (int nt = 0; nt < 8; nt++) {
#pragma unroll
                for (int i = 0; i < 4; i++) {
                    const int rowg = q0 + r0 + (i >= 2 ? 8 : 0);
                    const int colg = kt * 64 + nt * 8 + gc * 2 + (i & 1);
                    if (colg > rowg) sacc[nt][i] = -1e30f;
                }
            }
        }

        // ---- online softmax (register + quad shuffle) ----
        float mx0 = -1e30f, mx1 = -1e30f;
#pragma unroll
        for (int nt = 0; nt < 8; nt++) {
            mx0 = fmaxf(mx0, fmaxf(sacc[nt][0], sacc[nt][1]));
            mx1 = fmaxf(mx1, fmaxf(sacc[nt][2], sacc[nt][3]));
        }
        mx0 = fmaxf(mx0, __shfl_xor_sync(0xffffffffu, mx0, 1));
        mx0 = fmaxf(mx0, __shfl_xor_sync(0xffffffffu, mx0, 2));
        mx1 = fmaxf(mx1, __shfl_xor_sync(0xffffffffu, mx1, 1));
        mx1 = fmaxf(mx1, __shfl_xor_sync(0xffffffffu, mx1, 2));

        const float mn0 = fmaxf(m0v, mx0);
        const float mn1 = fmaxf(m1v, mx1);
        const float al0 = __expf(m0v - mn0);
        const float al1 = __expf(m1v - mn1);

        float sum0 = 0.f, sum1 = 0.f;
#pragma unroll
        for (int nt = 0; nt < 8; nt++) {
            float p0 = __expf(sacc[nt][0] - mn0);
            float p1 = __expf(sacc[nt][1] - mn0);
            float p2 = __expf(sacc[nt][2] - mn1);
            float p3 = __expf(sacc[nt][3] - mn1);
            sum0 += p0 + p1;
            sum1 += p2 + p3;
            const int col = nt * 8 + gc * 2;
            Ps[(r0)     * PP + col]     = f2tf32(p0);
            Ps[(r0)     * PP + col + 1] = f2tf32(p1);
            Ps[(r0 + 8) * PP + col]     = f2tf32(p2);
            Ps[(r0 + 8) * PP + col + 1] = f2tf32(p3);
        }
        sum0 += __shfl_xor_sync(0xffffffffu, sum0, 1);
        sum0 += __shfl_xor_sync(0xffffffffu, sum0, 2);
        sum1 += __shfl_xor_sync(0xffffffffu, sum1, 1);
        sum1 += __shfl_xor_sync(0xffffffffu, sum1, 2);

        l0 = l0 * al0 + sum0;
        l1 = l1 * al1 + sum1;
        m0v = mn0;
        m1v = mn1;

#pragma unroll
        for (int nt = 0; nt < 16; nt++) {
            oacc[nt][0] *= al0; oacc[nt][1] *= al0;
            oacc[nt][2] *= al1; oacc[nt][3] *= al1;
        }
        __syncwarp();   // order P stores before P loads (warp-private rows)

        // ---- O += P V ----
#pragma unroll
        for (int ks2 = 0; ks2 < 8; ks2++) {
            const int kk = ks2 * 8;
            uint32_t af[4];
            af[0] = Ps[(r0)     * PP + kk + gc];
            af[1] = Ps[(r0 + 8) * PP + kk + gc];
            af[2] = Ps[(r0)     * PP + kk + gc + 4];
            af[3] = Ps[(r0 + 8) * PP + kk + gc + 4];
#pragma unroll
            for (int nt = 0; nt < 16; nt++) {
                uint32_t bf[2];
                bf[0] = Vs[(kk + gc) * VP + nt * 8 + gr];
                bf[1] = Vs[(kk + gc + 4) * VP + nt * 8 + gr];
                mma_tf32_16x8x8(oacc[nt], af, bf);
            }
        }
        __syncthreads();   // all warps done before stage buffer reuse
    }

    // ---- epilogue: normalize + tf32-round + store to g_attn [B,T,C] ----
    const float inv0 = 1.f / l0;
    const float inv1 = 1.f / l1;
    const int t0 = q0 + r0;
    float* dst0 = g_attn + ((size_t)(b * 2048 + t0) * 2048) + h * 128;
    float* dst1 = g_attn + ((size_t)(b * 2048 + t0 + 8) * 2048) + h * 128;
#pragma unroll
    for (int nt = 0; nt < 16; nt++) {
        const int col = nt * 8 + gc * 2;
        *(float2*)(dst0 + col) = make_float2(roundtf(oacc[nt][0] * inv0),
                                             roundtf(oacc[nt][1] * inv0));
        *(float2*)(dst1 + col) = make_float2(roundtf(oacc[nt][2] * inv1),
                                             roundtf(oacc[nt][3] * inv1));
    }
}

// ---------------------------------------------------------------------------
extern "C" void kernel_launch(void* const* d_in, const int* in_sizes, int n_in,
                              void* d_out, int out_size)
{
    const float* x    = (const float*)d_in[0];
    const float* wq   = (const float*)d_in[1];
    const float* wk   = (const float*)d_in[2];
    const float* wv   = (const float*)d_in[3];
    const float* wo   = (const float*)d_in[4];
    const float* rc   = (const float*)d_in[5];
    const float* rs   = (const float*)d_in[6];
    float* out = (float*)d_out;

    (void)in_sizes; (void)n_in; (void)out_size;

    cudaFuncSetAttribute(qkv_gemm_mma_kernel,
                         cudaFuncAttributeMaxDynamicSharedMemorySize, GEMM_SMEM_BYTES);
    cudaFuncSetAttribute(out_gemm_mma_kernel,
                         cudaFuncAttributeMaxDynamicSharedMemorySize, GEMM_SMEM_BYTES);
    cudaFuncSetAttribute(flash_attn_mma_kernel,
                         cudaFuncAttributeMaxDynamicSharedMemorySize, FA_SMEM_BYTES);

    // 0. Pre-round inputs to tf32-representable fp32
    {
        float* xr = nullptr; float* wqr = nullptr; float* wkr = nullptr;
        float* wvr = nullptr; float* wor = nullptr;
        cudaGetSymbolAddress((void**)&xr,  g_xr);
        cudaGetSymbolAddress((void**)&wqr, g_wqr);
        cudaGetSymbolAddress((void**)&wkr, g_wkr);
        cudaGetSymbolAddress((void**)&wvr, g_wvr);
        cudaGetSymbolAddress((void**)&wor, g_wor);
        round_tf32_kernel<<<(4194304 + 255) / 256, 256>>>((const float4*)x,  (float4*)xr,  4194304);
        round_tf32_kernel<<<(1048576 + 255) / 256, 256>>>((const float4*)wq, (float4*)wqr, 1048576);
        round_tf32_kernel<<<(262144  + 255) / 256, 256>>>((const float4*)wk, (float4*)wkr, 262144);
        round_tf32_kernel<<<(262144  + 255) / 256, 256>>>((const float4*)wv, (float4*)wvr, 262144);
        round_tf32_kernel<<<(1048576 + 255) / 256, 256>>>((const float4*)wo, (float4*)wor, 1048576);
    }

    // 1. Fused QKV projection + RoPE -> g_q/g_k/g_v (tf32-rounded)
    qkv_gemm_mma_kernel<<<dim3(24, 64), 256, GEMM_SMEM_BYTES>>>(rc, rs);

    // 2. Causal flash attention -> g_attn (tf32-rounded)
    flash_attn_mma_kernel<<<dim3(16, 16, 4), 256, FA_SMEM_BYTES>>>();

    // 3. Output projection -> d_out
    out_gemm_mma_kernel<<<dim3(16, 64), 256, GEMM_SMEM_BYTES>>>(out);
}